// round 1
// baseline (speedup 1.0000x reference)
#include <cuda_runtime.h>

#define Nn   512
#define Vv   3889
#define Jj   35
#define NBb  20
#define PF   306
#define KTOT 326          // NBb + PF
#define VC   11667        // Vv*3
#define NJ3  105          // Jj*3

#define JOINTS_OFF (Nn*VC)               // 5973504
#define RS_OFF     (JOINTS_OFF + Nn*NJ3) // 6027264

// ---------------- scratch (static device globals; no runtime alloc) -----------
__device__ float g_pf[Nn*PF];        // pose feature (Rs[:,1:]-I) flattened
__device__ float g_vshaped[Nn*VC];
__device__ float g_vposed[Nn*VC];
__device__ float g_JrT[Jj*Vv];       // J_regressor transposed [j][v]
__device__ float g_WtT[Jj*Vv];       // weights transposed [j][v]
__device__ float g_Jp[Nn*NJ3];       // joints of v_shaped
__device__ float g_part[Nn*8*NJ3];   // split-V reduction partials
__device__ float g_A[Nn*Jj*12];      // 3x4 skinning transforms

// ---------------- K1: transpose J_regressor and weights ----------------------
__global__ void k_transpose(const float* __restrict__ Jr, const float* __restrict__ Wt) {
    int i = blockIdx.x * 256 + threadIdx.x;
    const int tot = Jj * Vv;
    if (i < tot) {
        int j = i / Vv, v = i % Vv;
        g_JrT[i] = Jr[v * Jj + j];
    } else if (i < 2 * tot) {
        int k = i - tot;
        int j = k / Vv, v = k % Vv;
        g_WtT[k] = Wt[v * Jj + j];
    }
}

// ---------------- K2: Rodrigues + pose feature --------------------------------
__global__ void k_rodrigues(const float* __restrict__ theta, float* __restrict__ rs_out) {
    int idx = blockIdx.x * 128 + threadIdx.x;
    if (idx >= Nn * Jj) return;
    int n = idx / Jj, j = idx % Jj;
    const float* th = theta + n * NJ3 + j * 3;
    float x = th[0], y = th[1], z = th[2];
    float ang = sqrtf(x * x + y * y + z * z + 1e-8f);
    float inv = 1.0f / ang;
    float rx = x * inv, ry = y * inv, rz = z * inv;
    float c = cosf(ang), s = sinf(ang);
    float ic = 1.0f - c;
    float R[9];
    R[0] = c + ic * rx * rx;  R[1] = ic * rx * ry - s * rz; R[2] = ic * rx * rz + s * ry;
    R[3] = ic * ry * rx + s * rz; R[4] = c + ic * ry * ry;  R[5] = ic * ry * rz - s * rx;
    R[6] = ic * rz * rx - s * ry; R[7] = ic * rz * ry + s * rx; R[8] = c + ic * rz * rz;
    float* ro = rs_out + (n * Jj + j) * 9;
    #pragma unroll
    for (int e = 0; e < 9; e++) ro[e] = R[e];
    if (j > 0) {
        float* pf = g_pf + n * PF + (j - 1) * 9;
        #pragma unroll
        for (int e = 0; e < 9; e++) pf[e] = R[e] - ((e == 0 || e == 4 || e == 8) ? 1.0f : 0.0f);
    }
}

// ---------------- K3: fused shape+pose GEMM -----------------------------------
// C[n, vc] = [beta | pf][n, 0:326] @ [shapedirs; posedirs][0:326, vc]
// Emits v_shaped (k<20 part + template + deform) and v_posed (full).
// Tile: 16 batch rows x 512 columns per block, 128 threads, 4 cols/thread.
__global__ void k_gemm(const float* __restrict__ beta, const float* __restrict__ vtemp,
                       const float* __restrict__ deform, const float* __restrict__ sdirs,
                       const float* __restrict__ pdirs) {
    __shared__ float As[KTOT * 16];  // [k][r], r contiguous
    const int t = threadIdx.x;
    const int nb = blockIdx.y * 16;
    for (int i = t; i < KTOT * 16; i += 128) {
        int k = i >> 4, r = i & 15, n = nb + r;
        As[i] = (k < NBb) ? beta[n * NBb + k] : g_pf[n * PF + (k - NBb)];
    }
    __syncthreads();

    const int c0 = blockIdx.x * 512 + t;
    float acc[16][4];
    #pragma unroll
    for (int r = 0; r < 16; r++)
        #pragma unroll
        for (int u = 0; u < 4; u++) acc[r][u] = 0.0f;

    // phase 1: shape (k < 20)
    for (int k = 0; k < NBb; k++) {
        float b[4];
        #pragma unroll
        for (int u = 0; u < 4; u++) {
            int c = c0 + 128 * u;
            b[u] = (c < VC) ? sdirs[k * VC + c] : 0.0f;
        }
        #pragma unroll
        for (int r = 0; r < 16; r++) {
            float a = As[k * 16 + r];
            #pragma unroll
            for (int u = 0; u < 4; u++) acc[r][u] = fmaf(a, b[u], acc[r][u]);
        }
    }
    // add template + deform, emit v_shaped, keep in regs
    #pragma unroll
    for (int u = 0; u < 4; u++) {
        int c = c0 + 128 * u;
        if (c < VC) {
            float vt = vtemp[c];
            #pragma unroll
            for (int r = 0; r < 16; r++) {
                float val = acc[r][u] + vt + deform[(nb + r) * VC + c];
                g_vshaped[(nb + r) * VC + c] = val;
                acc[r][u] = val;
            }
        }
    }
    // phase 2: pose (k in [20,326))
    for (int k = 0; k < PF; k++) {
        float b[4];
        #pragma unroll
        for (int u = 0; u < 4; u++) {
            int c = c0 + 128 * u;
            b[u] = (c < VC) ? pdirs[k * VC + c] : 0.0f;
        }
        #pragma unroll
        for (int r = 0; r < 16; r++) {
            float a = As[(k + NBb) * 16 + r];
            #pragma unroll
            for (int u = 0; u < 4; u++) acc[r][u] = fmaf(a, b[u], acc[r][u]);
        }
    }
    #pragma unroll
    for (int u = 0; u < 4; u++) {
        int c = c0 + 128 * u;
        if (c < VC) {
            #pragma unroll
            for (int r = 0; r < 16; r++) g_vposed[(nb + r) * VC + c] = acc[r][u];
        }
    }
}

// ---------------- K4: split-V J-regressor reduction (partials) ----------------
// Out[n,j,c] = sum_v X[n,v,c] * Jr[v,j].  mode 0: X=g_vshaped, mode 1: X=Xext.
__global__ void k_reduce_part(int mode, const float* __restrict__ Xext) {
    const float* X = (mode == 0) ? g_vshaped : Xext;
    int n = blockIdx.y, ch = blockIdx.x;
    int w = threadIdx.x >> 5, lane = threadIdx.x & 31;
    int j0 = w * 9;
    int nj = (Jj - j0 < 9) ? (Jj - j0) : 9;  // last warp: 8
    float acc[9][3];
    #pragma unroll
    for (int a = 0; a < 9; a++)
        #pragma unroll
        for (int c = 0; c < 3; c++) acc[a][c] = 0.0f;

    int v0 = ch * 487;
    int v1 = v0 + 487; if (v1 > Vv) v1 = Vv;
    const float* Xr = X + n * VC;
    for (int v = v0 + lane; v < v1; v += 32) {
        float x0 = Xr[v * 3 + 0], x1 = Xr[v * 3 + 1], x2 = Xr[v * 3 + 2];
        #pragma unroll
        for (int jj = 0; jj < 9; jj++) {
            if (jj < nj) {
                float rj = g_JrT[(j0 + jj) * Vv + v];
                acc[jj][0] = fmaf(rj, x0, acc[jj][0]);
                acc[jj][1] = fmaf(rj, x1, acc[jj][1]);
                acc[jj][2] = fmaf(rj, x2, acc[jj][2]);
            }
        }
    }
    #pragma unroll
    for (int jj = 0; jj < 9; jj++) {
        if (jj < nj) {
            #pragma unroll
            for (int c = 0; c < 3; c++) {
                float a = acc[jj][c];
                for (int o = 16; o; o >>= 1) a += __shfl_xor_sync(0xffffffffu, a, o);
                if (lane == 0) g_part[(n * 8 + ch) * NJ3 + (j0 + jj) * 3 + c] = a;
            }
        }
    }
}

__global__ void k_reduce_final(int mode, float* __restrict__ dstext) {
    int i = blockIdx.x * 128 + threadIdx.x;
    if (i >= Nn * NJ3) return;
    int n = i / NJ3;
    float s = 0.0f;
    #pragma unroll
    for (int ch = 0; ch < 8; ch++) s += g_part[(n * 8 + ch) * NJ3 + (i % NJ3)];
    if (mode == 0) g_Jp[i] = s; else dstext[i] = s;
}

// ---------------- K5: kinematic chain (thread per batch element) --------------
__global__ void k_kin(const float* __restrict__ rs, const float* __restrict__ scales,
                      const int* __restrict__ parents) {
    int n = blockIdx.x * 128 + threadIdx.x;
    if (n >= Nn) return;
    const float* R  = rs + n * Jj * 9;
    const float* Jp = g_Jp + n * NJ3;
    const float* sc = scales + n * NJ3;
    float G[Jj][12];
    // root
    #pragma unroll
    for (int a = 0; a < 3; a++) {
        G[0][a * 4 + 0] = R[a * 3 + 0];
        G[0][a * 4 + 1] = R[a * 3 + 1];
        G[0][a * 4 + 2] = R[a * 3 + 2];
        G[0][a * 4 + 3] = Jp[a];
    }
    for (int i = 1; i < Jj; i++) {
        int p = parents[i];
        float si0 = sc[i * 3 + 0], si1 = sc[i * 3 + 1], si2 = sc[i * 3 + 2];
        float ip0 = 1.0f / sc[p * 3 + 0], ip1 = 1.0f / sc[p * 3 + 1], ip2 = 1.0f / sc[p * 3 + 2];
        float rot[3][3];
        const float* Ri = R + i * 9;
        rot[0][0] = Ri[0] * si0 * ip0; rot[0][1] = Ri[1] * si1 * ip0; rot[0][2] = Ri[2] * si2 * ip0;
        rot[1][0] = Ri[3] * si0 * ip1; rot[1][1] = Ri[4] * si1 * ip1; rot[1][2] = Ri[5] * si2 * ip1;
        rot[2][0] = Ri[6] * si0 * ip2; rot[2][1] = Ri[7] * si1 * ip2; rot[2][2] = Ri[8] * si2 * ip2;
        float t0 = Jp[i * 3 + 0] - Jp[p * 3 + 0];
        float t1 = Jp[i * 3 + 1] - Jp[p * 3 + 1];
        float t2 = Jp[i * 3 + 2] - Jp[p * 3 + 2];
        #pragma unroll
        for (int a = 0; a < 3; a++) {
            float g0 = G[p][a * 4 + 0], g1 = G[p][a * 4 + 1], g2 = G[p][a * 4 + 2], g3 = G[p][a * 4 + 3];
            G[i][a * 4 + 0] = g0 * rot[0][0] + g1 * rot[1][0] + g2 * rot[2][0];
            G[i][a * 4 + 1] = g0 * rot[0][1] + g1 * rot[1][1] + g2 * rot[2][1];
            G[i][a * 4 + 2] = g0 * rot[0][2] + g1 * rot[1][2] + g2 * rot[2][2];
            G[i][a * 4 + 3] = g0 * t0 + g1 * t1 + g2 * t2 + g3;
        }
    }
    // A = G with last column adjusted by -G[:, :3] @ Jp_i
    float* gA = g_A + n * Jj * 12;
    for (int i = 0; i < Jj; i++) {
        float jx = Jp[i * 3 + 0], jy = Jp[i * 3 + 1], jz = Jp[i * 3 + 2];
        #pragma unroll
        for (int a = 0; a < 3; a++) {
            float g0 = G[i][a * 4 + 0], g1 = G[i][a * 4 + 1], g2 = G[i][a * 4 + 2];
            gA[i * 12 + a * 4 + 0] = g0;
            gA[i * 12 + a * 4 + 1] = g1;
            gA[i * 12 + a * 4 + 2] = g2;
            gA[i * 12 + a * 4 + 3] = G[i][a * 4 + 3] - (g0 * jx + g1 * jy + g2 * jz);
        }
    }
}

// ---------------- K6: skinning ------------------------------------------------
__global__ void k_skin(const float* __restrict__ trans, float* __restrict__ out) {
    __shared__ float As[Jj * 12];
    int n = blockIdx.y;
    for (int i = threadIdx.x; i < Jj * 12; i += 256) As[i] = g_A[n * Jj * 12 + i];
    __syncthreads();
    int vb = blockIdx.x * 1024 + threadIdx.x;
    float T[4][12];
    #pragma unroll
    for (int u = 0; u < 4; u++)
        #pragma unroll
        for (int e = 0; e < 12; e++) T[u][e] = 0.0f;

    for (int j = 0; j < Jj; j++) {
        float Aj[12];
        #pragma unroll
        for (int e = 0; e < 12; e++) Aj[e] = As[j * 12 + e];
        #pragma unroll
        for (int u = 0; u < 4; u++) {
            int v = vb + 256 * u;
            float wv = (v < Vv) ? g_WtT[j * Vv + v] : 0.0f;
            #pragma unroll
            for (int e = 0; e < 12; e++) T[u][e] = fmaf(wv, Aj[e], T[u][e]);
        }
    }
    float t0 = trans[n * 3 + 0], t1 = trans[n * 3 + 1], t2 = trans[n * 3 + 2];
    #pragma unroll
    for (int u = 0; u < 4; u++) {
        int v = vb + 256 * u;
        if (v < Vv) {
            float x = g_vposed[n * VC + v * 3 + 0];
            float y = g_vposed[n * VC + v * 3 + 1];
            float z = g_vposed[n * VC + v * 3 + 2];
            out[n * VC + v * 3 + 0] = fmaf(T[u][0], x, fmaf(T[u][1], y, fmaf(T[u][2],  z, T[u][3])))  + t0;
            out[n * VC + v * 3 + 1] = fmaf(T[u][4], x, fmaf(T[u][5], y, fmaf(T[u][6],  z, T[u][7])))  + t1;
            out[n * VC + v * 3 + 2] = fmaf(T[u][8], x, fmaf(T[u][9], y, fmaf(T[u][10], z, T[u][11]))) + t2;
        }
    }
}

// ---------------- launch -------------------------------------------------------
extern "C" void kernel_launch(void* const* d_in, const int* in_sizes, int n_in,
                              void* d_out, int out_size) {
    const float* beta     = (const float*)d_in[0];
    const float* theta    = (const float*)d_in[1];
    const float* scales   = (const float*)d_in[2];   // betas_extra (already exp'd)
    const float* deform   = (const float*)d_in[3];
    const float* trans    = (const float*)d_in[4];
    const float* vtemp    = (const float*)d_in[5];
    const float* sdirs    = (const float*)d_in[6];
    const float* pdirs    = (const float*)d_in[7];
    const float* Jr       = (const float*)d_in[8];
    const float* Wt       = (const float*)d_in[9];
    const int*   parents  = (const int*)d_in[10];
    float* out = (float*)d_out;

    k_transpose<<<(2 * Jj * Vv + 255) / 256, 256>>>(Jr, Wt);
    k_rodrigues<<<(Nn * Jj + 127) / 128, 128>>>(theta, out + RS_OFF);
    k_gemm<<<dim3((VC + 511) / 512, Nn / 16), 128>>>(beta, vtemp, deform, sdirs, pdirs);
    k_reduce_part<<<dim3(8, Nn), 128>>>(0, nullptr);
    k_reduce_final<<<(Nn * NJ3 + 127) / 128, 128>>>(0, nullptr);
    k_kin<<<(Nn + 127) / 128, 128>>>(out + RS_OFF, scales, parents);
    k_skin<<<dim3(4, Nn), 256>>>(trans, out);
    k_reduce_part<<<dim3(8, Nn), 128>>>(1, out);
    k_reduce_final<<<(Nn * NJ3 + 127) / 128, 128>>>(1, out + JOINTS_OFF);
}